// round 1
// baseline (speedup 1.0000x reference)
#include <cuda_runtime.h>
#include <cuda_bf16.h>
#include <math.h>

// Problem constants
#define BB 4
#define TT 1024
#define LL 12
#define HH 12
#define DD 768
#define HD 64
#define DF 3072
#define BT 4096          // B*T
#define NV 50257

// -------------------- scratch (device globals; no allocations) --------------------
__device__ float g_x  [BT * DD];            // residual stream
__device__ float g_ln [BT * DD];            // layernorm output
__device__ float g_qkv[BT * 3 * DD];        // qkv projections
__device__ float g_o  [BT * DD];            // attention output (pre out-proj)
__device__ float g_mlp[BT * DF];            // fc1 output
__device__ float g_att[(size_t)BB * HH * TT * TT];  // attention probs (201 MB)

// -------------------- embedding --------------------
__global__ void embed_kernel(const int* __restrict__ idx,
                             const float* __restrict__ wte,
                             const float* __restrict__ wpe,
                             float* __restrict__ x) {
    int i = blockIdx.x * 256 + threadIdx.x;   // 0 .. BT*DD-1
    if (i >= BT * DD) return;
    int bt = i / DD, d = i - bt * DD;
    int t = bt & (TT - 1);
    x[i] = wte[(size_t)idx[bt] * DD + d] + wpe[t * DD + d];
}

// -------------------- layernorm (one block per row) --------------------
__global__ __launch_bounds__(256) void ln_kernel(const float* __restrict__ in,
                                                 const float* __restrict__ g,
                                                 const float* __restrict__ b,
                                                 float* __restrict__ out) {
    int row = blockIdx.x;
    const float* x = in + (size_t)row * DD;
    float* y = out + (size_t)row * DD;
    int tid = threadIdx.x;
    float v[3];
    float s = 0.f, s2 = 0.f;
#pragma unroll
    for (int i = 0; i < 3; i++) {
        v[i] = x[tid + i * 256];
        s += v[i];
        s2 += v[i] * v[i];
    }
    __shared__ float rs[256], rs2[256];
    rs[tid] = s; rs2[tid] = s2;
    __syncthreads();
    for (int st = 128; st > 0; st >>= 1) {
        if (tid < st) { rs[tid] += rs[tid + st]; rs2[tid] += rs2[tid + st]; }
        __syncthreads();
    }
    float mu = rs[0] * (1.0f / DD);
    float var = rs2[0] * (1.0f / DD) - mu * mu;
    float rstd = rsqrtf(var + 1e-5f);
#pragma unroll
    for (int i = 0; i < 3; i++) {
        int c = tid + i * 256;
        y[c] = (v[i] - mu) * rstd * g[c] + b[c];
    }
}

// -------------------- SGEMM: C[M,N] = A[M,K] @ W[N,K]^T (+epilogue) --------------------
// EPI: 0 = none, 1 = add residual res[M,N], 2 = exact GELU
template <int EPI>
__global__ __launch_bounds__(256) void sgemm_kernel(const float* __restrict__ A,
                                                    const float* __restrict__ W,
                                                    const float* __restrict__ res,
                                                    float* __restrict__ C,
                                                    int M, int N, int K) {
    __shared__ float As[8][128];
    __shared__ float Bs[8][128];
    const int tid = threadIdx.x;
    const int bm = blockIdx.y * 128;
    const int bn = blockIdx.x * 128;
    const int tr = (tid / 16) * 8;   // row offset of thread tile
    const int tc = (tid % 16) * 8;   // col offset of thread tile
    const int lr = tid >> 1;         // 0..127 (tile row for loads)
    const int lc = (tid & 1) * 4;    // 0 or 4 (k offset for loads)

    const float* Aptr = A + (size_t)(bm + lr) * K + lc;
    const float* Wptr = W + (size_t)(bn + lr) * K + lc;
    const bool wvalid = (bn + lr) < N;

    float acc[8][8];
#pragma unroll
    for (int i = 0; i < 8; i++)
#pragma unroll
        for (int j = 0; j < 8; j++) acc[i][j] = 0.f;

    for (int k0 = 0; k0 < K; k0 += 8) {
        float4 a4 = *(const float4*)(Aptr + k0);
        float4 b4 = wvalid ? *(const float4*)(Wptr + k0) : make_float4(0.f, 0.f, 0.f, 0.f);
        As[lc + 0][lr] = a4.x; As[lc + 1][lr] = a4.y;
        As[lc + 2][lr] = a4.z; As[lc + 3][lr] = a4.w;
        Bs[lc + 0][lr] = b4.x; Bs[lc + 1][lr] = b4.y;
        Bs[lc + 2][lr] = b4.z; Bs[lc + 3][lr] = b4.w;
        __syncthreads();
#pragma unroll
        for (int kk = 0; kk < 8; kk++) {
            float ra[8], rb[8];
#pragma unroll
            for (int i = 0; i < 8; i++) ra[i] = As[kk][tr + i];
#pragma unroll
            for (int j = 0; j < 8; j++) rb[j] = Bs[kk][tc + j];
#pragma unroll
            for (int i = 0; i < 8; i++)
#pragma unroll
                for (int j = 0; j < 8; j++) acc[i][j] += ra[i] * rb[j];
        }
        __syncthreads();
    }

#pragma unroll
    for (int i = 0; i < 8; i++) {
        int m = bm + tr + i;
#pragma unroll
        for (int j = 0; j < 8; j++) {
            int n = bn + tc + j;
            if (n < N) {
                float v = acc[i][j];
                if (EPI == 1) v += res[(size_t)m * N + n];
                if (EPI == 2) v = 0.5f * v * (1.0f + erff(v * 0.70710678118654752f));
                C[(size_t)m * N + n] = v;
            }
        }
    }
}

// -------------------- attention: scores + causal softmax --------------------
// block = (bh, q); writes softmaxed probs into g_att row
__global__ __launch_bounds__(256) void attn_scores_kernel(const float* __restrict__ qkv,
                                                          float* __restrict__ att) {
    int bh = blockIdx.x;          // 0..47
    int q  = blockIdx.y;          // 0..1023
    int b = bh / HH, h = bh % HH;
    int tid = threadIdx.x;

    __shared__ float qs[HD];
    __shared__ float red[256];

    const float* base = qkv + (size_t)b * TT * (3 * DD);
    if (tid < HD) qs[tid] = base[(size_t)q * (3 * DD) + h * HD + tid] * 0.125f;  // 1/sqrt(64)
    __syncthreads();

    float* arow = att + ((size_t)bh * TT + q) * TT;

    float lmax = -1e30f;
    for (int k = tid; k <= q; k += 256) {
        const float* kv = base + (size_t)k * (3 * DD) + DD + h * HD;
        float s = 0.f;
#pragma unroll
        for (int d = 0; d < HD; d++) s += qs[d] * kv[d];
        arow[k] = s;
        lmax = fmaxf(lmax, s);
    }
    red[tid] = lmax; __syncthreads();
    for (int st = 128; st > 0; st >>= 1) {
        if (tid < st) red[tid] = fmaxf(red[tid], red[tid + st]);
        __syncthreads();
    }
    float mx = red[0];
    __syncthreads();

    float lsum = 0.f;
    for (int k = tid; k <= q; k += 256) {
        float e = __expf(arow[k] - mx);
        arow[k] = e;
        lsum += e;
    }
    red[tid] = lsum; __syncthreads();
    for (int st = 128; st > 0; st >>= 1) {
        if (tid < st) red[tid] += red[tid + st];
        __syncthreads();
    }
    float inv = 1.0f / red[0];

    for (int k = tid; k <= q; k += 256) arow[k] *= inv;
}

// -------------------- attention: O = P @ V --------------------
// block = (bh, q), 64 threads (one per head dim)
__global__ __launch_bounds__(64) void attn_pv_kernel(const float* __restrict__ qkv,
                                                     const float* __restrict__ att,
                                                     float* __restrict__ o) {
    int bh = blockIdx.x, q = blockIdx.y;
    int b = bh / HH, h = bh % HH;
    int d = threadIdx.x;

    const float* prow = att + ((size_t)bh * TT + q) * TT;
    const float* vbase = qkv + (size_t)b * TT * (3 * DD) + 2 * DD + h * HD + d;

    float a0 = 0.f, a1 = 0.f, a2 = 0.f, a3 = 0.f;
    int k = 0;
    int kend = q + 1;
    for (; k + 4 <= kend; k += 4) {
        a0 += prow[k + 0] * vbase[(size_t)(k + 0) * (3 * DD)];
        a1 += prow[k + 1] * vbase[(size_t)(k + 1) * (3 * DD)];
        a2 += prow[k + 2] * vbase[(size_t)(k + 2) * (3 * DD)];
        a3 += prow[k + 3] * vbase[(size_t)(k + 3) * (3 * DD)];
    }
    for (; k < kend; k++) a0 += prow[k] * vbase[(size_t)k * (3 * DD)];

    o[((size_t)b * TT + q) * DD + h * HD + d] = a0 + a1 + a2 + a3;
}

// -------------------- launch --------------------
extern "C" void kernel_launch(void* const* d_in, const int* in_sizes, int n_in,
                              void* d_out, int out_size) {
    const int*   idx   = (const int*)  d_in[0];
    const float* wte   = (const float*)d_in[1];
    const float* wpe   = (const float*)d_in[2];
    const float* ln1_g = (const float*)d_in[3];
    const float* ln1_b = (const float*)d_in[4];
    const float* qkv_w = (const float*)d_in[5];
    const float* out_w = (const float*)d_in[6];
    const float* ln2_g = (const float*)d_in[7];
    const float* ln2_b = (const float*)d_in[8];
    const float* fc1_w = (const float*)d_in[9];
    const float* fc2_w = (const float*)d_in[10];
    const float* lnf_g = (const float*)d_in[11];
    const float* lnf_b = (const float*)d_in[12];
    float* out = (float*)d_out;

    static float *p_x = nullptr, *p_ln = nullptr, *p_qkv = nullptr,
                 *p_o = nullptr, *p_mlp = nullptr, *p_att = nullptr;
    if (!p_x) {
        cudaGetSymbolAddress((void**)&p_x,   g_x);
        cudaGetSymbolAddress((void**)&p_ln,  g_ln);
        cudaGetSymbolAddress((void**)&p_qkv, g_qkv);
        cudaGetSymbolAddress((void**)&p_o,   g_o);
        cudaGetSymbolAddress((void**)&p_mlp, g_mlp);
        cudaGetSymbolAddress((void**)&p_att, g_att);
    }

    // embedding
    embed_kernel<<<(BT * DD + 255) / 256, 256>>>(idx, wte, wpe, p_x);

    dim3 grid_qkv(3 * DD / 128, BT / 128);   // (18, 32)
    dim3 grid_d  (DD / 128, BT / 128);       // (6, 32)
    dim3 grid_f  (DF / 128, BT / 128);       // (24, 32)
    dim3 grid_v  ((NV + 127) / 128, BT / 128); // (393, 32)
    dim3 grid_att(BB * HH, TT);              // (48, 1024)

    for (int l = 0; l < LL; l++) {
        // ln1
        ln_kernel<<<BT, 256>>>(p_x, ln1_g + l * DD, ln1_b + l * DD, p_ln);
        // qkv projection
        sgemm_kernel<0><<<grid_qkv, 256>>>(p_ln, qkv_w + (size_t)l * 3 * DD * DD,
                                           nullptr, p_qkv, BT, 3 * DD, DD);
        // attention
        attn_scores_kernel<<<grid_att, 256>>>(p_qkv, p_att);
        attn_pv_kernel<<<grid_att, 64>>>(p_qkv, p_att, p_o);
        // output projection + residual (in-place into x)
        sgemm_kernel<1><<<grid_d, 256>>>(p_o, out_w + (size_t)l * DD * DD,
                                         p_x, p_x, BT, DD, DD);
        // ln2
        ln_kernel<<<BT, 256>>>(p_x, ln2_g + l * DD, ln2_b + l * DD, p_ln);
        // fc1 + gelu
        sgemm_kernel<2><<<grid_f, 256>>>(p_ln, fc1_w + (size_t)l * DF * DD,
                                         nullptr, p_mlp, BT, DF, DD);
        // fc2 + residual
        sgemm_kernel<1><<<grid_d, 256>>>(p_mlp, fc2_w + (size_t)l * DD * DF,
                                         p_x, p_x, BT, DD, DF);
    }

    // final layernorm
    ln_kernel<<<BT, 256>>>(p_x, lnf_g, lnf_b, p_ln);
    // lm_head (tied with wte)
    sgemm_kernel<0><<<grid_v, 256>>>(p_ln, wte, nullptr, out, BT, NV, DD);
}

// round 5
// speedup vs baseline: 6.5449x; 6.5449x over previous
#include <cuda_runtime.h>
#include <cuda_bf16.h>
#include <math.h>
#include <stdint.h>

// Problem constants
#define BB 4
#define TT 1024
#define LL 12
#define HH 12
#define DD 768
#define HD 64
#define DF 3072
#define BT 4096          // B*T
#define NV 50257

// -------------------- scratch (device globals; no allocations) --------------------
__device__ float g_x  [BT * DD];            // residual stream
__device__ float g_ln [BT * DD];            // layernorm output
__device__ float g_qkv[BT * 3 * DD];        // qkv projections
__device__ float g_o  [BT * DD];            // attention output (pre out-proj)
__device__ float g_mlp[BT * DF];            // fc1 output

// -------------------- embedding --------------------
__global__ void embed_kernel(const int* __restrict__ idx,
                             const float* __restrict__ wte,
                             const float* __restrict__ wpe,
                             float* __restrict__ x) {
    int i = blockIdx.x * 256 + threadIdx.x;
    if (i >= BT * DD) return;
    int bt = i / DD, d = i - bt * DD;
    int t = bt & (TT - 1);
    x[i] = wte[(size_t)idx[bt] * DD + d] + wpe[t * DD + d];
}

// -------------------- layernorm (one block per row) --------------------
__global__ __launch_bounds__(256) void ln_kernel(const float* __restrict__ in,
                                                 const float* __restrict__ g,
                                                 const float* __restrict__ b,
                                                 float* __restrict__ out) {
    int row = blockIdx.x;
    const float* x = in + (size_t)row * DD;
    float* y = out + (size_t)row * DD;
    int tid = threadIdx.x;
    float v[3];
    float s = 0.f, s2 = 0.f;
#pragma unroll
    for (int i = 0; i < 3; i++) {
        v[i] = x[tid + i * 256];
        s += v[i];
        s2 += v[i] * v[i];
    }
    __shared__ float rs[256], rs2[256];
    rs[tid] = s; rs2[tid] = s2;
    __syncthreads();
    for (int st = 128; st > 0; st >>= 1) {
        if (tid < st) { rs[tid] += rs[tid + st]; rs2[tid] += rs2[tid + st]; }
        __syncthreads();
    }
    float mu = rs[0] * (1.0f / DD);
    float var = rs2[0] * (1.0f / DD) - mu * mu;
    float rstd = rsqrtf(var + 1e-5f);
#pragma unroll
    for (int i = 0; i < 3; i++) {
        int c = tid + i * 256;
        y[c] = (v[i] - mu) * rstd * g[c] + b[c];
    }
}

// -------------------- tf32 conversion helper --------------------
__device__ __forceinline__ unsigned int f2tf32(float f) {
    unsigned int r;
    asm("cvt.rna.tf32.f32 %0, %1;" : "=r"(r) : "f"(f));
    return r;
}

// -------------------- TF32 tensor-core GEMM: C[M,N] = A[M,K] @ W[N,K]^T --------------------
// EPI: 0 = none, 1 = add residual res[M,N], 2 = exact GELU
// BM=BN=128, BK=16, 256 threads, warp tile 32x64 (m16n8k8 atoms: 2x8 per warp).
#define TGS 20   // smem row stride (16 + 4 pad) -> conflict-free fragment LDS
template <int EPI>
__global__ __launch_bounds__(256, 2) void tgemm_kernel(const float* __restrict__ A,
                                                       const float* __restrict__ W,
                                                       const float* __restrict__ res,
                                                       float* __restrict__ C,
                                                       int M, int N, int K) {
    __shared__ unsigned int As[2][128 * TGS];
    __shared__ unsigned int Bs[2][128 * TGS];

    const int tid  = threadIdx.x;
    const int bm   = blockIdx.y * 128;
    const int bn   = blockIdx.x * 128;
    const int warp = tid >> 5;
    const int lane = tid & 31;
    const int wm   = (warp >> 1) * 32;   // 4 warps along m
    const int wn   = (warp & 1) * 64;    // 2 warps along n
    const int g    = lane >> 2;          // groupID
    const int tg   = lane & 3;           // thread in group

    float acc[2][8][4];
#pragma unroll
    for (int mi = 0; mi < 2; mi++)
#pragma unroll
        for (int ni = 0; ni < 8; ni++)
#pragma unroll
            for (int r = 0; r < 4; r++) acc[mi][ni][r] = 0.f;

    // per-thread load coords: 2048 floats per tile = 512 float4; 2 per thread
    const int r0 = (tid + 0)   >> 2, kq0 = (tid + 0)   & 3;
    const int r1 = (tid + 256) >> 2, kq1 = (tid + 256) & 3;
    const bool bv0 = (bn + r0) < N;
    const bool bv1 = (bn + r1) < N;

    const int nk = K >> 4;
    float4 pa0, pa1, pb0, pb1;

    // prefetch tile 0
    {
        pa0 = *(const float4*)(A + (size_t)(bm + r0) * K + kq0 * 4);
        pa1 = *(const float4*)(A + (size_t)(bm + r1) * K + kq1 * 4);
        pb0 = bv0 ? *(const float4*)(W + (size_t)(bn + r0) * K + kq0 * 4)
                  : make_float4(0.f, 0.f, 0.f, 0.f);
        pb1 = bv1 ? *(const float4*)(W + (size_t)(bn + r1) * K + kq1 * 4)
                  : make_float4(0.f, 0.f, 0.f, 0.f);
    }
    // store tile 0 into buffer 0
    {
        unsigned int* a = &As[0][r0 * TGS + kq0 * 4];
        a[0] = f2tf32(pa0.x); a[1] = f2tf32(pa0.y); a[2] = f2tf32(pa0.z); a[3] = f2tf32(pa0.w);
        a = &As[0][r1 * TGS + kq1 * 4];
        a[0] = f2tf32(pa1.x); a[1] = f2tf32(pa1.y); a[2] = f2tf32(pa1.z); a[3] = f2tf32(pa1.w);
        unsigned int* b = &Bs[0][r0 * TGS + kq0 * 4];
        b[0] = f2tf32(pb0.x); b[1] = f2tf32(pb0.y); b[2] = f2tf32(pb0.z); b[3] = f2tf32(pb0.w);
        b = &Bs[0][r1 * TGS + kq1 * 4];
        b[0] = f2tf32(pb1.x); b[1] = f2tf32(pb1.y); b[2] = f2tf32(pb1.z); b[3] = f2tf32(pb1.w);
    }
    __syncthreads();

    for (int it = 0; it < nk; it++) {
        const int buf = it & 1;
        // prefetch next tile from gmem
        if (it + 1 < nk) {
            int k0 = (it + 1) << 4;
            pa0 = *(const float4*)(A + (size_t)(bm + r0) * K + k0 + kq0 * 4);
            pa1 = *(const float4*)(A + (size_t)(bm + r1) * K + k0 + kq1 * 4);
            pb0 = bv0 ? *(const float4*)(W + (size_t)(bn + r0) * K + k0 + kq0 * 4)
                      : make_float4(0.f, 0.f, 0.f, 0.f);
            pb1 = bv1 ? *(const float4*)(W + (size_t)(bn + r1) * K + k0 + kq1 * 4)
                      : make_float4(0.f, 0.f, 0.f, 0.f);
        }
        // compute on current buffer
#pragma unroll
        for (int ka = 0; ka < 16; ka += 8) {
            unsigned int afr[2][4];
#pragma unroll
            for (int mi = 0; mi < 2; mi++) {
                const unsigned int* ab = &As[buf][(wm + mi * 16 + g) * TGS + ka + tg];
                afr[mi][0] = ab[0];
                afr[mi][1] = ab[8 * TGS];
                afr[mi][2] = ab[4];
                afr[mi][3] = ab[8 * TGS + 4];
            }
            unsigned int bfr[8][2];
#pragma unroll
            for (int ni = 0; ni < 8; ni++) {
                const unsigned int* bb = &Bs[buf][(wn + ni * 8 + g) * TGS + ka + tg];
                bfr[ni][0] = bb[0];
                bfr[ni][1] = bb[4];
            }
#pragma unroll
            for (int mi = 0; mi < 2; mi++)
#pragma unroll
                for (int ni = 0; ni < 8; ni++) {
                    float* c = acc[mi][ni];
                    asm volatile(
                        "mma.sync.aligned.m16n8k8.row.col.f32.tf32.tf32.f32 "
                        "{%0,%1,%2,%3}, {%4,%5,%6,%7}, {%8,%9}, {%0,%1,%2,%3};"
                        : "+f"(c[0]), "+f"(c[1]), "+f"(c[2]), "+f"(c[3])
                        : "r"(afr[mi][0]), "r"(afr[mi][1]), "r"(afr[mi][2]), "r"(afr[mi][3]),
                          "r"(bfr[ni][0]), "r"(bfr[ni][1]));
                }
        }
        // store prefetched tile into other buffer
        if (it + 1 < nk) {
            const int nb = buf ^ 1;
            unsigned int* a = &As[nb][r0 * TGS + kq0 * 4];
            a[0] = f2tf32(pa0.x); a[1] = f2tf32(pa0.y); a[2] = f2tf32(pa0.z); a[3] = f2tf32(pa0.w);
            a = &As[nb][r1 * TGS + kq1 * 4];
            a[0] = f2tf32(pa1.x); a[1] = f2tf32(pa1.y); a[2] = f2tf32(pa1.z); a[3] = f2tf32(pa1.w);
            unsigned int* b = &Bs[nb][r0 * TGS + kq0 * 4];
            b[0] = f2tf32(pb0.x); b[1] = f2tf32(pb0.y); b[2] = f2tf32(pb0.z); b[3] = f2tf32(pb0.w);
            b = &Bs[nb][r1 * TGS + kq1 * 4];
            b[0] = f2tf32(pb1.x); b[1] = f2tf32(pb1.y); b[2] = f2tf32(pb1.z); b[3] = f2tf32(pb1.w);
            __syncthreads();
        }
    }

    // epilogue
#pragma unroll
    for (int mi = 0; mi < 2; mi++) {
        int row0 = bm + wm + mi * 16 + g;
#pragma unroll
        for (int ni = 0; ni < 8; ni++) {
            int col0 = bn + wn + ni * 8 + tg * 2;
#pragma unroll
            for (int rr = 0; rr < 2; rr++) {      // row pair (g, g+8)
                int m = row0 + rr * 8;
#pragma unroll
                for (int cc = 0; cc < 2; cc++) {  // col pair
                    int n = col0 + cc;
                    if (n < N) {
                        float v = acc[mi][ni][rr * 2 + cc];
                        if (EPI == 1) v += res[(size_t)m * N + n];
                        if (EPI == 2) v = 0.5f * v * (1.0f + erff(v * 0.70710678118654752f));
                        C[(size_t)m * N + n] = v;
                    }
                }
            }
        }
    }
}

// -------------------- flash attention --------------------
// block = (bh, q-tile of 64). 256 threads as 16x16 grid: each thread owns 4q x 4k / 4q x 4d.
#define ATS 68   // smem row stride (64 + 4)
__global__ __launch_bounds__(256) void flash_attn_kernel(const float* __restrict__ qkv,
                                                         float* __restrict__ o) {
    extern __shared__ float sm[];
    float* Qs = sm;
    float* Ks = sm + 64 * ATS;
    float* Vs = sm + 2 * 64 * ATS;
    float* Ps = sm + 3 * 64 * ATS;

    const int bh = blockIdx.x;          // 0..47
    const int qt = blockIdx.y;          // 0..15
    const int b = bh / HH, h = bh % HH;
    const int tid = threadIdx.x;
    const int tx = tid & 15;            // k / d group
    const int ty = tid >> 4;            // q group

    const float* base = qkv + (size_t)b * TT * (3 * DD);

    // load Q tile (scaled by 1/sqrt(hd))
#pragma unroll
    for (int p = 0; p < 4; p++) {
        int id = p * 256 + tid;
        int row = id >> 4, c4 = (id & 15) * 4;
        float4 v = *(const float4*)(base + (size_t)(qt * 64 + row) * (3 * DD) + h * HD + c4);
        float* q = &Qs[row * ATS + c4];
        q[0] = v.x * 0.125f; q[1] = v.y * 0.125f; q[2] = v.z * 0.125f; q[3] = v.w * 0.125f;
    }

    float m_i[4], l_i[4], acc[4][4];
#pragma unroll
    for (int i = 0; i < 4; i++) {
        m_i[i] = -1e30f; l_i[i] = 0.f;
#pragma unroll
        for (int j = 0; j < 4; j++) acc[i][j] = 0.f;
    }

    for (int kt = 0; kt <= qt; kt++) {
        __syncthreads();   // previous PV done / Q load done
        // load K and V tiles
#pragma unroll
        for (int p = 0; p < 4; p++) {
            int id = p * 256 + tid;
            int row = id >> 4, c4 = (id & 15) * 4;
            const float* src = base + (size_t)(kt * 64 + row) * (3 * DD) + h * HD + c4;
            float4 kv = *(const float4*)(src + DD);
            float4 vv = *(const float4*)(src + 2 * DD);
            *(float4*)&Ks[row * ATS + c4] = kv;
            *(float4*)&Vs[row * ATS + c4] = vv;
        }
        __syncthreads();

        // S = Q K^T  (4q x 4k per thread)
        float s[4][4];
#pragma unroll
        for (int i = 0; i < 4; i++)
#pragma unroll
            for (int j = 0; j < 4; j++) s[i][j] = 0.f;
        for (int d = 0; d < 64; d += 4) {
            float4 qv[4], kv[4];
#pragma unroll
            for (int i = 0; i < 4; i++) qv[i] = *(float4*)&Qs[(ty * 4 + i) * ATS + d];
#pragma unroll
            for (int j = 0; j < 4; j++) kv[j] = *(float4*)&Ks[(tx * 4 + j) * ATS + d];
#pragma unroll
            for (int i = 0; i < 4; i++)
#pragma unroll
                for (int j = 0; j < 4; j++)
                    s[i][j] += qv[i].x * kv[j].x + qv[i].y * kv[j].y
                             + qv[i].z * kv[j].z + qv[i].w * kv[j].w;
        }

        // causal mask on diagonal tile
        if (kt == qt) {
#pragma unroll
            for (int i = 0; i < 4; i++)
#pragma unroll
                for (int j = 0; j < 4; j++)
                    if (tx * 4 + j > ty * 4 + i) s[i][j] = -1e30f;
        }

        // online softmax per q row (reduce across 16 tx lanes)
#pragma unroll
        for (int i = 0; i < 4; i++) {
            float mx = fmaxf(fmaxf(s[i][0], s[i][1]), fmaxf(s[i][2], s[i][3]));
#pragma unroll
            for (int off = 1; off < 16; off <<= 1)
                mx = fmaxf(mx, __shfl_xor_sync(0xffffffffu, mx, off));
            float mnew = fmaxf(m_i[i], mx);
            float corr = __expf(m_i[i] - mnew);
            float rs = 0.f;
            float pvals[4];
#pragma unroll
            for (int j = 0; j < 4; j++) {
                float p = __expf(s[i][j] - mnew);
                pvals[j] = p; rs += p;
            }
#pragma unroll
            for (int off = 1; off < 16; off <<= 1)
                rs += __shfl_xor_sync(0xffffffffu, rs, off);
            l_i[i] = l_i[i] * corr + rs;
            m_i[i] = mnew;
#pragma unroll
            for (int j = 0; j < 4; j++) acc[i][j] *= corr;
            *(float4*)&Ps[(ty * 4 + i) * ATS + tx * 4] =
                make_float4(pvals[0], pvals[1], pvals[2], pvals[3]);
        }
        __syncthreads();

        // O += P @ V  (thread owns 4q x 4d, d0 = tx*4)
        for (int k = 0; k < 64; k += 4) {
            float4 pv[4], vv[4];
#pragma unroll
            for (int i = 0; i < 4; i++) pv[i] = *(float4*)&Ps[(ty * 4 + i) * ATS + k];
#pragma unroll
            for (int j = 0; j < 4; j++) vv[j] = *(float4*)&Vs[(k + j) * ATS + tx * 4];
#pragma unroll
            for (int i = 0; i < 4; i++) {
#pragma unroll
                for (int j = 0; j < 4; j++) {
                    float p = (j == 0) ? pv[i].x : (j == 1) ? pv[i].y : (j == 2) ? pv[i].z : pv[i].w;
                    acc[i][0] += p * vv[j].x;
                    acc[i][1] += p * vv[j].y;
                    acc[i][2] += p * vv[j].z;
                    acc[i][3] += p * vv[j].w;
                }
            }
        }
    }

    // write O
#pragma unroll
    for (int i = 0; i < 4; i++) {
        float inv = 1.0f / l_i[i];
        int t = qt * 64 + ty * 4 + i;
        float* dst = o + ((size_t)b * TT + t) * DD + h * HD + tx * 4;
        dst[0] = acc[i][0] * inv;
        dst[1] = acc[i][1] * inv;
        dst[2] = acc[i][2] * inv;
        dst[3] = acc[i][3] * inv;
    }
}

// -------------------- launch --------------------
extern "C" void kernel_launch(void* const* d_in, const int* in_sizes, int n_in,
                              void* d_out, int out_size) {
    const int*   idx   = (const int*)  d_in[0];
    const float* wte   = (const float*)d_in[1];
    const float* wpe   = (const float*)d_in[2];
    const float* ln1_g = (const float*)d_in[3];
    const float* ln1_b = (const float*)d_in[4];
    const float* qkv_w = (const float*)d_in[5];
    const float* out_w = (const float*)d_in[6];
    const float* ln2_g = (const float*)d_in[7];
    const float* ln2_b = (const float*)d_in[8];
    const float* fc1_w = (const float*)d_in[9];
    const float* fc2_w = (const float*)d_in[10];
    const float* lnf_g = (const float*)d_in[11];
    const float* lnf_b = (const float*)d_in[12];
    float* out = (float*)d_out;

    static float *p_x = nullptr, *p_ln = nullptr, *p_qkv = nullptr,
                 *p_o = nullptr, *p_mlp = nullptr;
    static const int ATT_SMEM = 4 * 64 * ATS * (int)sizeof(float);
    if (!p_x) {
        cudaGetSymbolAddress((void**)&p_x,   g_x);
        cudaGetSymbolAddress((void**)&p_ln,  g_ln);
        cudaGetSymbolAddress((void**)&p_qkv, g_qkv);
        cudaGetSymbolAddress((void**)&p_o,   g_o);
        cudaGetSymbolAddress((void**)&p_mlp, g_mlp);
        cudaFuncSetAttribute(flash_attn_kernel,
                             cudaFuncAttributeMaxDynamicSharedMemorySize, ATT_SMEM);
    }

    embed_kernel<<<(BT * DD + 255) / 256, 256>>>(idx, wte, wpe, p_x);

    dim3 grid_qkv(3 * DD / 128, BT / 128);     // (18, 32)
    dim3 grid_d  (DD / 128, BT / 128);         // (6, 32)
    dim3 grid_f  (DF / 128, BT / 128);         // (24, 32)
    dim3 grid_v  ((NV + 127) / 128, BT / 128); // (393, 32)
    dim3 grid_att(BB * HH, TT / 64);           // (48, 16)

    for (int l = 0; l < LL; l++) {
        ln_kernel<<<BT, 256>>>(p_x, ln1_g + l * DD, ln1_b + l * DD, p_ln);
        tgemm_kernel<0><<<grid_qkv, 256>>>(p_ln, qkv_w + (size_t)l * 3 * DD * DD,
                                           nullptr, p_qkv, BT, 3 * DD, DD);
        flash_attn_kernel<<<grid_att, 256, ATT_SMEM>>>(p_qkv, p_o);
        tgemm_kernel<1><<<grid_d, 256>>>(p_o, out_w + (size_t)l * DD * DD,
                                         p_x, p_x, BT, DD, DD);
        ln_kernel<<<BT, 256>>>(p_x, ln2_g + l * DD, ln2_b + l * DD, p_ln);
        tgemm_kernel<2><<<grid_f, 256>>>(p_ln, fc1_w + (size_t)l * DF * DD,
                                         nullptr, p_mlp, BT, DF, DD);
        tgemm_kernel<1><<<grid_d, 256>>>(p_mlp, fc2_w + (size_t)l * DD * DF,
                                         p_x, p_x, BT, DD, DF);
    }

    ln_kernel<<<BT, 256>>>(p_x, lnf_g, lnf_b, p_ln);
    tgemm_kernel<0><<<grid_v, 256>>>(p_ln, wte, nullptr, out, BT, NV, DD);
}